// round 6
// baseline (speedup 1.0000x reference)
#include <cuda_runtime.h>

// out = -weight * sum_{k=0}^{M-1} f[k]*f[k+D] / (N-1),  M = (N-1)*D, D=2000.
//
// Persistent grid with dynamic 32KB-chunk stealing + PREFETCHED chunk ids:
// thread 0 grabs chunk c+1's id (atomicAdd) before the block streams chunk c,
// so the atomic round-trip is hidden behind ~6.5us of loads instead of
// stalling all 8 warps at the chunk boundary. Double-buffered s_next/s_warp
// keep it at ONE __syncthreads per chunk.
// Determinism: partials keyed by CHUNK id, fixed intra-chunk and final order.

#define NBLOCKS 1216
#define NTHREADS 256
#define CHUNK 2048            // float4 per chunk = 32KB
#define MAXCHUNKS 16384

__device__ float g_chunk_sum[MAXCHUNKS];
__device__ unsigned int g_next = 0;
__device__ unsigned int g_done = 0;

__global__ __launch_bounds__(NTHREADS)
void shifted_dot_dyn2(const float4* __restrict__ in4, long long Mv, int Dv,
                      int nchunks,
                      const float* __restrict__ weight, float* __restrict__ out,
                      float inv_nm1) {
    __shared__ unsigned int s_next[2];
    __shared__ float s_warp[2][NTHREADS / 32];

    if (threadIdx.x == 0) s_next[0] = atomicAdd(&g_next, 1u);
    __syncthreads();
    int par = 0;
    unsigned int c = s_next[0];

    while (c < (unsigned int)nchunks) {
        // Prefetch next chunk id immediately; latency hides behind the loads.
        if (threadIdx.x == 0) s_next[par ^ 1] = atomicAdd(&g_next, 1u);

        const long long beg = (long long)c * CHUNK;
        long long end = beg + CHUNK;
        if (end > Mv) end = Mv;

        float acc = 0.0f;
        long long t = beg + threadIdx.x;
        for (; t + 3 * NTHREADS < end; t += 4 * NTHREADS) {
            float4 a0 = in4[t];
            float4 a1 = in4[t + NTHREADS];
            float4 a2 = in4[t + 2 * NTHREADS];
            float4 a3 = in4[t + 3 * NTHREADS];
            float4 b0 = in4[t + Dv];
            float4 b1 = in4[t + NTHREADS + Dv];
            float4 b2 = in4[t + 2 * NTHREADS + Dv];
            float4 b3 = in4[t + 3 * NTHREADS + Dv];
            acc += a0.x * b0.x + a0.y * b0.y + a0.z * b0.z + a0.w * b0.w;
            acc += a1.x * b1.x + a1.y * b1.y + a1.z * b1.z + a1.w * b1.w;
            acc += a2.x * b2.x + a2.y * b2.y + a2.z * b2.z + a2.w * b2.w;
            acc += a3.x * b3.x + a3.y * b3.y + a3.z * b3.z + a3.w * b3.w;
        }
        for (; t < end; t += NTHREADS) {
            float4 a = in4[t];
            float4 b = in4[t + Dv];
            acc += a.x * b.x + a.y * b.y + a.z * b.z + a.w * b.w;
        }

        // warp reduce -> per-warp partial in double-buffered smem
        #pragma unroll
        for (int o = 16; o > 0; o >>= 1)
            acc += __shfl_xor_sync(0xffffffff, acc, o);
        if ((threadIdx.x & 31) == 0) s_warp[par][threadIdx.x >> 5] = acc;
        __syncthreads();   // one barrier per chunk

        if (threadIdx.x == 0) {
            float v = 0.0f;
            #pragma unroll
            for (int i = 0; i < NTHREADS / 32; i++) v += s_warp[par][i];
            g_chunk_sum[c] = v;
        }
        par ^= 1;
        c = s_next[par];   // prefetched id (written pre-loads, visible via bar)
    }

    // last block to finish does the fixed-order final reduction
    __shared__ bool is_last;
    if (threadIdx.x == 0) {
        __threadfence();
        unsigned int old = atomicAdd(&g_done, 1u);
        is_last = (old == gridDim.x - 1);
    }
    __syncthreads();

    if (is_last) {
        const volatile float* p = g_chunk_sum;
        float v = 0.0f;
        for (int i = threadIdx.x; i < nchunks; i += NTHREADS)
            v += p[i];
        #pragma unroll
        for (int o = 16; o > 0; o >>= 1)
            v += __shfl_xor_sync(0xffffffff, v, o);
        __shared__ float s2[NTHREADS / 32];
        if ((threadIdx.x & 31) == 0) s2[threadIdx.x >> 5] = v;
        __syncthreads();
        if (threadIdx.x == 0) {
            float tot = 0.0f;
            #pragma unroll
            for (int i = 0; i < NTHREADS / 32; i++) tot += s2[i];
            out[0] = -(*weight) * tot * inv_nm1;
            g_next = 0;   // reset for next graph replay
            g_done = 0;
        }
    }
}

extern "C" void kernel_launch(void* const* d_in, const int* in_sizes, int n_in,
                              void* d_out, int out_size) {
    const float* factor = (const float*)d_in[0];
    const float* weight = (const float*)d_in[1];
    float* out = (float*)d_out;

    const int D = 2000;
    const long long total = (long long)in_sizes[0];   // N * D
    const long long N = total / D;
    const long long M = (N - 1) * (long long)D;       // divisible by 4
    const long long Mv = M / 4;                       // float4 count
    const int Dv = D / 4;
    const int nchunks = (int)((Mv + CHUNK - 1) / CHUNK);  // ~16000 <= MAXCHUNKS

    shifted_dot_dyn2<<<NBLOCKS, NTHREADS>>>(
        (const float4*)factor, Mv, Dv, nchunks, weight, out,
        1.0f / (float)(N - 1));
}

// round 8
// speedup vs baseline: 1.0617x; 1.0617x over previous
#include <cuda_runtime.h>

// out = -weight * sum_{k=0}^{M-1} f[k]*f[k+D] / (N-1),  M = (N-1)*D, D=2000.
//
// Persistent grid + dynamic 32KB-chunk stealing. Per-thread register
// accumulator carried ACROSS chunks: the per-chunk smem reduce + load-drain
// barrier is gone, so chunk boundaries no longer empty the memory pipeline
// (previous version starved DRAM ~25% of cycles at synchronized boundaries).
// Chunk-id handoff: thread0 atomic -> double-buffered smem slot -> one
// __syncthreads (id visibility only; no data dependency, no drain).
// Contiguous 32KB chunk sweep keeps the +8KB b-stream L1-resident.

#define NBLOCKS 1216
#define NTHREADS 256
#define CHUNK 2048            // float4 per chunk = 32KB

__device__ float g_partials[NBLOCKS];
__device__ unsigned int g_next = 0;
__device__ unsigned int g_done = 0;

__global__ __launch_bounds__(NTHREADS)
void shifted_dot_dyn3(const float4* __restrict__ in4, long long Mv, int Dv,
                      int nchunks,
                      const float* __restrict__ weight, float* __restrict__ out,
                      float inv_nm1) {
    __shared__ unsigned int s_next[2];

    if (threadIdx.x == 0) s_next[0] = atomicAdd(&g_next, 1u);
    __syncthreads();
    int par = 0;
    unsigned int c = s_next[0];

    float acc = 0.0f;

    while (c < (unsigned int)nchunks) {
        // Prefetch next chunk id; hides atomic latency behind the streaming.
        if (threadIdx.x == 0) s_next[par ^ 1] = atomicAdd(&g_next, 1u);

        const long long beg = (long long)c * CHUNK;
        long long end = beg + CHUNK;
        if (end > Mv) end = Mv;

        long long t = beg + threadIdx.x;
        for (; t + 3 * NTHREADS < end; t += 4 * NTHREADS) {
            float4 a0 = in4[t];
            float4 a1 = in4[t + NTHREADS];
            float4 a2 = in4[t + 2 * NTHREADS];
            float4 a3 = in4[t + 3 * NTHREADS];
            float4 b0 = in4[t + Dv];
            float4 b1 = in4[t + NTHREADS + Dv];
            float4 b2 = in4[t + 2 * NTHREADS + Dv];
            float4 b3 = in4[t + 3 * NTHREADS + Dv];
            acc += a0.x * b0.x + a0.y * b0.y + a0.z * b0.z + a0.w * b0.w;
            acc += a1.x * b1.x + a1.y * b1.y + a1.z * b1.z + a1.w * b1.w;
            acc += a2.x * b2.x + a2.y * b2.y + a2.z * b2.z + a2.w * b2.w;
            acc += a3.x * b3.x + a3.y * b3.y + a3.z * b3.z + a3.w * b3.w;
        }
        for (; t < end; t += NTHREADS) {
            float4 a = in4[t];
            float4 b = in4[t + Dv];
            acc += a.x * b.x + a.y * b.y + a.z * b.z + a.w * b.w;
        }

        __syncthreads();        // id visibility only — no data drain
        par ^= 1;
        c = s_next[par];
    }

    // One block reduction at the very end.
    #pragma unroll
    for (int o = 16; o > 0; o >>= 1)
        acc += __shfl_xor_sync(0xffffffff, acc, o);

    __shared__ float s[NTHREADS / 32];
    if ((threadIdx.x & 31) == 0) s[threadIdx.x >> 5] = acc;
    __syncthreads();

    __shared__ bool is_last;
    if (threadIdx.x == 0) {
        float v = 0.0f;
        #pragma unroll
        for (int i = 0; i < NTHREADS / 32; i++) v += s[i];
        g_partials[blockIdx.x] = v;
        __threadfence();
        unsigned int old = atomicAdd(&g_done, 1u);
        is_last = (old == gridDim.x - 1);
    }
    __syncthreads();

    if (is_last) {
        const volatile float* p = g_partials;
        float v = 0.0f;
        for (int i = threadIdx.x; i < (int)gridDim.x; i += NTHREADS)
            v += p[i];
        #pragma unroll
        for (int o = 16; o > 0; o >>= 1)
            v += __shfl_xor_sync(0xffffffff, v, o);

        __shared__ float s2[NTHREADS / 32];
        if ((threadIdx.x & 31) == 0) s2[threadIdx.x >> 5] = v;
        __syncthreads();
        if (threadIdx.x == 0) {
            float tot = 0.0f;
            #pragma unroll
            for (int i = 0; i < NTHREADS / 32; i++) tot += s2[i];
            out[0] = -(*weight) * tot * inv_nm1;
            g_next = 0;   // reset for next graph replay
            g_done = 0;
        }
    }
}

extern "C" void kernel_launch(void* const* d_in, const int* in_sizes, int n_in,
                              void* d_out, int out_size) {
    const float* factor = (const float*)d_in[0];
    const float* weight = (const float*)d_in[1];
    float* out = (float*)d_out;

    const int D = 2000;
    const long long total = (long long)in_sizes[0];   // N * D
    const long long N = total / D;
    const long long M = (N - 1) * (long long)D;       // divisible by 4
    const long long Mv = M / 4;                       // float4 count
    const int Dv = D / 4;
    const int nchunks = (int)((Mv + CHUNK - 1) / CHUNK);

    shifted_dot_dyn3<<<NBLOCKS, NTHREADS>>>(
        (const float4*)factor, Mv, Dv, nchunks, weight, out,
        1.0f / (float)(N - 1));
}